// round 11
// baseline (speedup 1.0000x reference)
#include <cuda_runtime.h>
#include <cuda_fp16.h>
#include <cstdint>

#define BATCH 16384
#define NN    1024
#define EE    8
#define RR    64
#define ER    512
#define LL    3
#define NBX   (BATCH / 128)     // 128 row blocks
#define NJOBS (128 + 1664 + 1664 + 1536)   // 4992

// ---------------- static device scratch ----------------
__device__ float   g_xcur[BATCH * NN];
__device__ float   g_gates[BATCH * EE];
__device__ __half  g_xh[BATCH * NN];
__device__ __half  g_cph[BATCH * ER];
__device__ __half  g_Vh[LL * ER * NN];
__device__ __half  g_Uh[LL * NN * ER];
__device__ __half  g_Ch[LL * EE * RR * RR];
// scheduler state
__device__ int g_ticket;
__device__ int g_cntG1[LL * NBX];
__device__ int g_cntG2[LL * NBX];
__device__ int g_gatesDone[LL * NBX];

// ---------------- helpers ----------------
__device__ __forceinline__ uint32_t smem_u32(const void* p) {
    uint32_t a;
    asm("{ .reg .u64 t; cvta.to.shared.u64 t, %1; cvt.u32.u64 %0, t; }" : "=r"(a) : "l"(p));
    return a;
}
__device__ __forceinline__ void ldsm4(uint32_t* r, uint32_t addr) {
    asm volatile("ldmatrix.sync.aligned.m8n8.x4.shared.b16 {%0,%1,%2,%3}, [%4];"
                 : "=r"(r[0]), "=r"(r[1]), "=r"(r[2]), "=r"(r[3]) : "r"(addr));
}
__device__ __forceinline__ void mma_f16(float* d, const uint32_t* a, const uint32_t* b) {
    asm volatile(
        "mma.sync.aligned.m16n8k16.row.col.f32.f16.f16.f32 "
        "{%0,%1,%2,%3}, {%4,%5,%6,%7}, {%8,%9}, {%0,%1,%2,%3};"
        : "+f"(d[0]), "+f"(d[1]), "+f"(d[2]), "+f"(d[3])
        : "r"(a[0]), "r"(a[1]), "r"(a[2]), "r"(a[3]), "r"(b[0]), "r"(b[1]));
}
__device__ __forceinline__ uint32_t hpack2(float a, float b) {
    __half ha = __float2half_rn(a), hb = __float2half_rn(b);
    return (uint32_t)__half_as_ushort(ha) | ((uint32_t)__half_as_ushort(hb) << 16);
}
__device__ __forceinline__ void cp16(uint32_t dst, const void* src) {
    asm volatile("cp.async.cg.shared.global [%0], [%1], 16;" :: "r"(dst), "l"(src));
}
#define CP_COMMIT() asm volatile("cp.async.commit_group;" ::: "memory")
#define CP_WAIT1()  asm volatile("cp.async.wait_group 1;" ::: "memory")
#define CP_WAIT0()  asm volatile("cp.async.wait_group 0;" ::: "memory")

// ---------------- prep kernels ----------------
__global__ void zero_k() {
    int i = blockIdx.x * 256 + threadIdx.x;
    if (i < LL * NBX) { g_cntG1[i] = 0; g_cntG2[i] = 0; g_gatesDone[i] = 0; }
    if (i == 0) g_ticket = 0;
}
__global__ void prep_x(const float* __restrict__ x) {
    int i = blockIdx.x * 256 + threadIdx.x;
    g_xh[i] = __float2half_rn(x[i]);
}
__global__ void prepV_k(const float* __restrict__ V) {
    int i = blockIdx.x * 256 + threadIdx.x;
    g_Vh[i] = __float2half_rn(V[i]);
}
__global__ void prepC_k(const float* __restrict__ C) {
    int i = blockIdx.x * 256 + threadIdx.x;
    g_Ch[i] = __float2half_rn(C[i]);
}
__global__ void prepU_k(const float* __restrict__ U) {
    int o = blockIdx.x * 256 + threadIdx.x;     // o = (l*NN + n)*ER + er
    int er = o & 511, n = (o >> 9) & 1023, l = o >> 19;
    g_Uh[o] = __float2half_rn(U[(((size_t)(l * EE + (er >> 6))) * NN + n) * RR + (er & 63)]);
}

// ---------------- scheduler sync helpers ----------------
__device__ __forceinline__ void wait_cnt(int* cnt, int target, int t) {
    if (t == 0) {
        while (atomicAdd(cnt, 0) < target) __nanosleep(64);
        __threadfence();
    }
    __syncthreads();
}
__device__ __forceinline__ void mark_cnt(int* cnt, int t) {
    __syncthreads();
    if (t == 0) { __threadfence(); atomicAdd(cnt, 1); }
}

// ---------------- stage layout (bytes) ----------------
// per stage (36864): A[128][144] @0, B[128][144] @18432 ; 3 stages; K-chunk 64
#define STG   36864
#define S_BH  18432
#define RV_H(el)  ((el) * 18432)
#define OCT       36864
#define SM_SZ     110592

__device__ __forceinline__ void stage_panels(
    uint32_t sbase, char* smc_unused, int t,
    const __half* A, int strideA, const __half* B, int strideB) {
    const int row = t >> 3;
    const uint32_t seg = (uint32_t)(t & 7) * 16;
#pragma unroll
    for (int it = 0; it < 4; it++) {
        int r = it * 32 + row;
        cp16(sbase + (uint32_t)r * 144 + seg, (const char*)(A + (size_t)r * strideA) + seg);
        cp16(sbase + S_BH + (uint32_t)r * 144 + seg,
             (const char*)(B + (size_t)r * strideB) + seg);
    }
}

__device__ __forceinline__ void mma_block128(uint32_t base, int wm, int wn, int lr, int kc,
                                             float d[2][8][4]) {
    const uint32_t Ah = base, Bh = base + S_BH;
#pragma unroll
    for (int q = 0; q < 4; q++) {
        uint32_t ah[2][4];
#pragma unroll
        for (int i = 0; i < 2; i++) {
            uint32_t ra = (uint32_t)((wm + i * 16 + lr) * 144 + (q * 16 + kc) * 2);
            ldsm4(ah[i], Ah + ra);
        }
        uint32_t bh[8][2];
#pragma unroll
        for (int jj = 0; jj < 4; jj++) {
            uint32_t rb = (uint32_t)((wn + jj * 16 + lr) * 144 + (q * 16 + kc) * 2);
            uint32_t tp[4];
            ldsm4(tp, Bh + rb);
            bh[2 * jj][0] = tp[0]; bh[2 * jj + 1][0] = tp[1];
            bh[2 * jj][1] = tp[2]; bh[2 * jj + 1][1] = tp[3];
        }
#pragma unroll
        for (int i = 0; i < 2; i++)
#pragma unroll
            for (int j = 0; j < 8; j++)
                mma_f16(d[i][j], ah[i], bh[j]);
    }
}

#define MAINLOOP(NK, pA, sA, pB, sB)                                          \
    stage_panels(sb, smc, t, pA, sA, pB, sB); CP_COMMIT();                    \
    stage_panels(sb + STG, smc, t, pA + 64, sA, pB + 64, sB); CP_COMMIT();    \
    _Pragma("unroll 1")                                                       \
    for (int kt = 0; kt < (NK); kt++) {                                       \
        if (kt + 1 < (NK)) { CP_WAIT1(); } else { CP_WAIT0(); }               \
        __syncthreads();                                                      \
        if (kt + 2 < (NK)) {                                                  \
            int bi = (kt + 2) % 3;                                            \
            stage_panels(sb + (uint32_t)bi * STG, smc, t,                     \
                         pA + (kt + 2) * 64, sA, pB + (kt + 2) * 64, sB);     \
            CP_COMMIT();                                                      \
        }                                                                     \
        mma_block128(sb + (uint32_t)(kt % 3) * STG, wm, wn, lr, kc, d);       \
    }

// ---------------- job bodies ----------------

// gates: 128 rows of softmax(x_l @ gw^T), exact fp32
__device__ void job_gates(int l, int bx, const float* __restrict__ x_in,
                          const float* __restrict__ gw, int t) {
    const float* xl = l ? g_xcur : x_in;
    const int w = t >> 5, lane = t & 31;
    const size_t brow0 = (size_t)bx * 128;
#pragma unroll 1
    for (int rr = 0; rr < 16; rr++) {
        size_t row = brow0 + (size_t)w * 16 + rr;
        const float4* xr = (const float4*)(xl + row * NN);
        float acc[EE];
#pragma unroll
        for (int e = 0; e < EE; e++) acc[e] = 0.f;
#pragma unroll
        for (int i = 0; i < 8; i++) {
            float4 xv = xr[i * 32 + lane];
#pragma unroll
            for (int e = 0; e < EE; e++) {
                float4 wv = ((const float4*)(gw + e * NN))[i * 32 + lane];
                acc[e] += xv.x * wv.x + xv.y * wv.y + xv.z * wv.z + xv.w * wv.w;
            }
        }
#pragma unroll
        for (int off = 16; off > 0; off >>= 1)
#pragma unroll
            for (int e = 0; e < EE; e++) acc[e] += __shfl_xor_sync(0xffffffffu, acc[e], off);
        if (lane == 0) {
            float m = acc[0];
#pragma unroll
            for (int e = 1; e < EE; e++) m = fmaxf(m, acc[e]);
            float s = 0.f, pe[EE];
#pragma unroll
            for (int e = 0; e < EE; e++) { pe[e] = __expf(acc[e] - m); s += pe[e]; }
            float inv = 1.0f / s;
#pragma unroll
            for (int e = 0; e < EE; e++) g_gates[row * EE + e] = pe[e] * inv;
        }
    }
}

// gemm1 + fused expert chain -> c'
__device__ void job_g1(int l, int bx, int ey, char* smc, uint32_t sb, int t) {
    const int w = t >> 5, lane = t & 31;
    const int lr = lane & 15, kc = (lane >> 4) * 8, g = lane >> 2, tig = lane & 3;
    const int wm = (w & 3) * 32, wn = (w >> 2) * 64;
    const size_t brow0 = (size_t)bx * 128;

    const __half* pA = g_xh + brow0 * NN;
    const __half* pB = g_Vh + (size_t)l * ER * NN + (size_t)(ey * 128) * NN;

    float d[2][8][4];
#pragma unroll
    for (int i = 0; i < 2; i++)
#pragma unroll
        for (int j = 0; j < 8; j++)
#pragma unroll
            for (int k = 0; k < 4; k++) d[i][j][k] = 0.f;

    MAINLOOP(16, pA, NN, pB, NN)
    __syncthreads();

    const int el = w >> 2;
    {
#pragma unroll
        for (int i = 0; i < 2; i++) {
            int r0 = wm + i * 16 + g;
#pragma unroll
            for (int j = 0; j < 8; j++) {
                int c = j * 8 + 2 * tig;
                uint32_t h0 = hpack2(fmaxf(d[i][j][0], 0.f), fmaxf(d[i][j][1], 0.f));
                uint32_t h1 = hpack2(fmaxf(d[i][j][2], 0.f), fmaxf(d[i][j][3], 0.f));
                uint32_t o0 = (uint32_t)(r0 * 144 + c * 2);
                *(uint32_t*)(smc + RV_H(el) + o0)           = h0;
                *(uint32_t*)(smc + RV_H(el) + o0 + 8 * 144) = h1;
            }
        }
    }
    {
        int el2 = t >> 7, r = (t >> 1) & 63, hf = t & 1;
        const __half* sH = g_Ch +
            (((size_t)(l * EE + ey * 2 + el2)) * RR + r) * RR + hf * 32;
        char* dH = smc + OCT + el2 * 9216 + r * 144 + hf * 64;
#pragma unroll
        for (int s4 = 0; s4 < 4; s4++)
            *(uint4*)(dH + s4 * 16) = *(const uint4*)(sH + s4 * 8);
    }
    __syncthreads();

#pragma unroll
    for (int i = 0; i < 2; i++)
#pragma unroll
        for (int j = 0; j < 8; j++)
#pragma unroll
            for (int k = 0; k < 4; k++) d[i][j][k] = 0.f;
    {
        const uint32_t Ah = sb + RV_H(el);
        const uint32_t Bh = sb + OCT + el * 9216;
#pragma unroll
        for (int q = 0; q < 4; q++) {
            uint32_t ah[2][4];
#pragma unroll
            for (int i = 0; i < 2; i++) {
                uint32_t ra = (uint32_t)((wm + i * 16 + lr) * 144 + (q * 16 + kc) * 2);
                ldsm4(ah[i], Ah + ra);
            }
            uint32_t bh[8][2];
#pragma unroll
            for (int jj = 0; jj < 4; jj++) {
                uint32_t rb = (uint32_t)((jj * 16 + lr) * 144 + (q * 16 + kc) * 2);
                uint32_t tp[4];
                ldsm4(tp, Bh + rb);
                bh[2 * jj][0] = tp[0]; bh[2 * jj + 1][0] = tp[1];
                bh[2 * jj][1] = tp[2]; bh[2 * jj + 1][1] = tp[3];
            }
#pragma unroll
            for (int i = 0; i < 2; i++)
#pragma unroll
                for (int j = 0; j < 8; j++)
                    mma_f16(d[i][j], ah[i], bh[j]);
        }
    }

    {
        const int e = ey * 2 + el;
#pragma unroll
        for (int i = 0; i < 2; i++) {
            size_t r0 = brow0 + wm + i * 16 + g, r1 = r0 + 8;
            float g0 = g_gates[r0 * EE + e], g1 = g_gates[r1 * EE + e];
#pragma unroll
            for (int j = 0; j < 8; j++) {
                int cc = e * 64 + j * 8 + 2 * tig;
                *(uint32_t*)(g_cph + r0 * ER + cc) =
                    hpack2(g0 * fmaxf(d[i][j][0], 0.f), g0 * fmaxf(d[i][j][1], 0.f));
                *(uint32_t*)(g_cph + r1 * ER + cc) =
                    hpack2(g1 * fmaxf(d[i][j][2], 0.f), g1 * fmaxf(d[i][j][3], 0.f));
            }
        }
    }
}

// gemm2 + residual epilogue
__device__ void job_g2(int l, int bx, int ny, char* smc, uint32_t sb, int t,
                       const float* __restrict__ x_in, const float* __restrict__ biasg,
                       float* __restrict__ outg) {
    const int w = t >> 5, lane = t & 31;
    const int lr = lane & 15, kc = (lane >> 4) * 8, g = lane >> 2, tig = lane & 3;
    const int wm = (w & 3) * 32, wn = (w >> 2) * 64;
    const size_t brow0 = (size_t)bx * 128;
    const int no = ny * 128;

    const __half* pA = g_cph + brow0 * ER;
    const __half* pB = g_Uh + (size_t)l * NN * ER + (size_t)no * ER;

    float d[2][8][4];
#pragma unroll
    for (int i = 0; i < 2; i++)
#pragma unroll
        for (int j = 0; j < 8; j++)
#pragma unroll
            for (int k = 0; k < 4; k++) d[i][j][k] = 0.f;

    MAINLOOP(8, pA, ER, pB, ER)

    const float* xl = l ? g_xcur : x_in;
    float* dst = (l == LL - 1) ? outg : g_xcur;
#pragma unroll
    for (int i = 0; i < 2; i++) {
        size_t r0 = brow0 + wm + i * 16 + g, r1 = r0 + 8;
#pragma unroll
        for (int j = 0; j < 8; j++) {
            int c0 = no + wn + j * 8 + 2 * tig;
            float2 bv = *(const float2*)(biasg + l * NN + c0);
            {
                float2 xv = *(const float2*)(x_in + r0 * NN + c0);
                float2 lv = *(const float2*)(xl + r0 * NN + c0);
                float o0 = fmaf(xv.x, d[i][j][0] + bv.x, lv.x);
                float o1 = fmaf(xv.y, d[i][j][1] + bv.y, lv.y);
                *(float2*)(dst + r0 * NN + c0) = make_float2(o0, o1);
                if (l < LL - 1)
                    *(uint32_t*)(g_xh + r0 * NN + c0) = hpack2(o0, o1);
            }
            {
                float2 xv = *(const float2*)(x_in + r1 * NN + c0);
                float2 lv = *(const float2*)(xl + r1 * NN + c0);
                float o0 = fmaf(xv.x, d[i][j][2] + bv.x, lv.x);
                float o1 = fmaf(xv.y, d[i][j][3] + bv.y, lv.y);
                *(float2*)(dst + r1 * NN + c0) = make_float2(o0, o1);
                if (l < LL - 1)
                    *(uint32_t*)(g_xh + r1 * NN + c0) = hpack2(o0, o1);
            }
        }
    }
}

// =====================================================================
// Persistent mega-kernel: dynamic job queue with dependency counters.
// Queue order per layer l: [g1 x512 (bx-major)], then per bx: 8 g2 jobs
// followed by gates(l+1,bx). Layer-0 gates (no deps) lead the queue.
// Deps are always earlier tickets => deadlock-free.
// =====================================================================
__global__ void __launch_bounds__(256, 2)
mega_k(const float* __restrict__ x_in, const float* __restrict__ gw,
       const float* __restrict__ biasg, float* __restrict__ outg) {
    extern __shared__ char smc[];
    const uint32_t sb = smem_u32(smc);
    const int t = threadIdx.x;
    __shared__ int s_job;

    for (;;) {
        if (t == 0) s_job = atomicAdd(&g_ticket, 1);
        __syncthreads();
        int jid = s_job;
        if (jid >= NJOBS) break;

        // ---- decode ----
        int typ, l, bx, sub = 0;
        if (jid < 128) { typ = 0; l = 0; bx = jid; }
        else {
            int j = jid - 128;
            if (j < 1664)      { l = 0; }
            else if (j < 3328) { l = 1; j -= 1664; }
            else               { l = 2; j -= 3328; }
            if (j < 512) { typ = 1; bx = j >> 2; sub = j & 3; }
            else {
                j -= 512;
                if (l < 2) {
                    bx = j / 9; int k = j - bx * 9;
                    if (k < 8) { typ = 2; sub = k; }
                    else       { typ = 0; l = l + 1; }
                } else { typ = 2; bx = j >> 3; sub = j & 7; }
            }
        }

        // ---- wait deps, run, mark done ----
        if (typ == 0) {
            if (l > 0) wait_cnt(&g_cntG2[(l - 1) * NBX + bx], 8, t);
            else __syncthreads();
            job_gates(l, bx, x_in, gw, t);
            __syncthreads();
            if (t == 0) { __threadfence(); atomicExch(&g_gatesDone[l * NBX + bx], 1); }
        } else if (typ == 1) {
            wait_cnt(&g_gatesDone[l * NBX + bx], 1, t);
            job_g1(l, bx, sub, smc, sb, t);
            mark_cnt(&g_cntG1[l * NBX + bx], t);
        } else {
            wait_cnt(&g_cntG1[l * NBX + bx], 4, t);
            job_g2(l, bx, sub, smc, sb, t, x_in, biasg, outg);
            mark_cnt(&g_cntG2[l * NBX + bx], t);
        }
        __syncthreads();
    }
}

// =====================================================================
extern "C" void kernel_launch(void* const* d_in, const int* in_sizes, int n_in,
                              void* d_out, int out_size) {
    const float* x    = (const float*)d_in[0];
    const float* U    = (const float*)d_in[1];
    const float* V    = (const float*)d_in[2];
    const float* C    = (const float*)d_in[3];
    const float* bias = (const float*)d_in[4];
    const float* gw   = (const float*)d_in[5];
    float* out = (float*)d_out;

    zero_k<<<2, 256>>>();
    prep_x<<<BATCH * NN / 256, 256>>>(x);
    prepV_k<<<LL * ER * NN / 256, 256>>>(V);
    prepU_k<<<LL * NN * ER / 256, 256>>>(U);
    prepC_k<<<LL * EE * RR * RR / 256, 256>>>(C);

    cudaFuncSetAttribute(mega_k, cudaFuncAttributeMaxDynamicSharedMemorySize, SM_SZ);
    mega_k<<<304, 256, SM_SZ>>>(x, gw, bias, out);
}

// round 12
// speedup vs baseline: 1.1688x; 1.1688x over previous
#include <cuda_runtime.h>
#include <cuda_fp16.h>
#include <cstdint>

#define BATCH 16384
#define NN    1024
#define EE    8
#define RR    64
#define ER    512
#define LL    3

// ---------------- static device scratch ----------------
__device__ float   g_xcur[BATCH * NN];
__device__ float   g_gates[BATCH * EE];
__device__ __half  g_xh[BATCH * NN];            // x_l fp16
__device__ __half  g_cph[BATCH * ER];           // c' fp16
__device__ __half  g_Vh[LL * ER * NN];          // weights fp16
__device__ __half  g_Uh[LL * NN * ER];
__device__ __half  g_Ch[LL * EE * RR * RR];

// ---------------- helpers ----------------
__device__ __forceinline__ uint32_t smem_u32(const void* p) {
    uint32_t a;
    asm("{ .reg .u64 t; cvta.to.shared.u64 t, %1; cvt.u32.u64 %0, t; }" : "=r"(a) : "l"(p));
    return a;
}
__device__ __forceinline__ void ldsm4(uint32_t* r, uint32_t addr) {
    asm volatile("ldmatrix.sync.aligned.m8n8.x4.shared.b16 {%0,%1,%2,%3}, [%4];"
                 : "=r"(r[0]), "=r"(r[1]), "=r"(r[2]), "=r"(r[3]) : "r"(addr));
}
__device__ __forceinline__ void mma_f16(float* d, const uint32_t* a, const uint32_t* b) {
    asm volatile(
        "mma.sync.aligned.m16n8k16.row.col.f32.f16.f16.f32 "
        "{%0,%1,%2,%3}, {%4,%5,%6,%7}, {%8,%9}, {%0,%1,%2,%3};"
        : "+f"(d[0]), "+f"(d[1]), "+f"(d[2]), "+f"(d[3])
        : "r"(a[0]), "r"(a[1]), "r"(a[2]), "r"(a[3]), "r"(b[0]), "r"(b[1]));
}
__device__ __forceinline__ uint32_t hpack2(float a, float b) {
    __half ha = __float2half_rn(a), hb = __float2half_rn(b);
    return (uint32_t)__half_as_ushort(ha) | ((uint32_t)__half_as_ushort(hb) << 16);
}
__device__ __forceinline__ float2 hunpack2(uint32_t v) {
    __half2 h = *reinterpret_cast<__half2*>(&v);
    return __half22float2(h);
}
__device__ __forceinline__ void cp16(uint32_t dst, const void* src) {
    asm volatile("cp.async.cg.shared.global [%0], [%1], 16;" :: "r"(dst), "l"(src));
}
#define CP_COMMIT() asm volatile("cp.async.commit_group;" ::: "memory")
#define CP_WAIT1()  asm volatile("cp.async.wait_group 1;" ::: "memory")
#define CP_WAIT0()  asm volatile("cp.async.wait_group 0;" ::: "memory")

// ---------------- prep kernels ----------------
__global__ void prep_x(const float* __restrict__ x) {
    int i = blockIdx.x * 256 + threadIdx.x;
    g_xh[i] = __float2half_rn(x[i]);
}
__global__ void prepV_k(const float* __restrict__ V) {
    int i = blockIdx.x * 256 + threadIdx.x;
    g_Vh[i] = __float2half_rn(V[i]);
}
__global__ void prepC_k(const float* __restrict__ C) {
    int i = blockIdx.x * 256 + threadIdx.x;
    g_Ch[i] = __float2half_rn(C[i]);
}
__global__ void prepU_k(const float* __restrict__ U) {
    int o = blockIdx.x * 256 + threadIdx.x;     // o = (l*NN + n)*ER + er
    int er = o & 511, n = (o >> 9) & 1023, l = o >> 19;
    g_Uh[o] = __float2half_rn(U[(((size_t)(l * EE + (er >> 6))) * NN + n) * RR + (er & 63)]);
}

// ---------------- gates: fp16 x_l (g_xh), fp32 gw, fp32 accumulation ----------------
__global__ void gates_k(const float* __restrict__ gw) {
    int w = threadIdx.x >> 5, lane = threadIdx.x & 31;
    size_t row = (size_t)blockIdx.x * 8 + w;
    const uint4* xr = (const uint4*)(g_xh + row * NN);   // 8 halves per uint4
    float acc[EE];
#pragma unroll
    for (int e = 0; e < EE; e++) acc[e] = 0.f;
#pragma unroll
    for (int i = 0; i < 4; i++) {
        uint4 xv = xr[lane + 32 * i];
        float2 f0 = hunpack2(xv.x), f1 = hunpack2(xv.y);
        float2 f2 = hunpack2(xv.z), f3 = hunpack2(xv.w);
#pragma unroll
        for (int e = 0; e < EE; e++) {
            const float4* wp = (const float4*)(gw + e * NN) + (lane + 32 * i) * 2;
            float4 w0 = wp[0], w1 = wp[1];
            acc[e] += f0.x * w0.x + f0.y * w0.y + f1.x * w0.z + f1.y * w0.w
                    + f2.x * w1.x + f2.y * w1.y + f3.x * w1.z + f3.y * w1.w;
        }
    }
#pragma unroll
    for (int off = 16; off > 0; off >>= 1)
#pragma unroll
        for (int e = 0; e < EE; e++) acc[e] += __shfl_xor_sync(0xffffffffu, acc[e], off);
    if (lane == 0) {
        float m = acc[0];
#pragma unroll
        for (int e = 1; e < EE; e++) m = fmaxf(m, acc[e]);
        float s = 0.f, pe[EE];
#pragma unroll
        for (int e = 0; e < EE; e++) { pe[e] = __expf(acc[e] - m); s += pe[e]; }
        float inv = 1.0f / s;
#pragma unroll
        for (int e = 0; e < EE; e++) g_gates[row * EE + e] = pe[e] * inv;
    }
}

// ---------------- stage layout (bytes) ----------------
// per stage (36864): A[128][144] @0, B[128][144] @18432 ; 3 stages; K-chunk 64
#define STG   36864
#define S_BH  18432
// gemm1 expert phase (after mainloop, reuse smem from 0):
#define RV_H(el)  ((el) * 18432)            // rv: 128x144 fp16 per expert
#define OCT       36864                     // C tiles: el*9216
#define SM_SZ     110592

// cp.async stage: A 128 rows x 128B, B 128 rows x 128B  (8 cp16 / thread)
__device__ __forceinline__ void stage_panels(
    uint32_t sbase, int t,
    const __half* A, int strideA, const __half* B, int strideB) {
    const int row = t >> 3;                       // 0..31
    const uint32_t seg = (uint32_t)(t & 7) * 16;  // 0..112
#pragma unroll
    for (int it = 0; it < 4; it++) {
        int r = it * 32 + row;
        cp16(sbase + (uint32_t)r * 144 + seg, (const char*)(A + (size_t)r * strideA) + seg);
        cp16(sbase + S_BH + (uint32_t)r * 144 + seg,
             (const char*)(B + (size_t)r * strideB) + seg);
    }
}

// ---------------- 128x128 tile, one k64 chunk; warp tile 32x64 ----------------
__device__ __forceinline__ void mma_block128(uint32_t base, int wm, int wn, int lr, int kc,
                                             float d[2][8][4]) {
    const uint32_t Ah = base, Bh = base + S_BH;
#pragma unroll
    for (int q = 0; q < 4; q++) {
        uint32_t ah[2][4];
#pragma unroll
        for (int i = 0; i < 2; i++) {
            uint32_t ra = (uint32_t)((wm + i * 16 + lr) * 144 + (q * 16 + kc) * 2);
            ldsm4(ah[i], Ah + ra);
        }
        uint32_t bh[8][2];
#pragma unroll
        for (int jj = 0; jj < 4; jj++) {
            uint32_t rb = (uint32_t)((wn + jj * 16 + lr) * 144 + (q * 16 + kc) * 2);
            uint32_t tp[4];
            ldsm4(tp, Bh + rb);
            bh[2 * jj][0] = tp[0]; bh[2 * jj + 1][0] = tp[1];
            bh[2 * jj][1] = tp[2]; bh[2 * jj + 1][1] = tp[3];
        }
#pragma unroll
        for (int i = 0; i < 2; i++)
#pragma unroll
            for (int j = 0; j < 8; j++)
                mma_f16(d[i][j], ah[i], bh[j]);
    }
}

// 3-buffer mainloop, ONE __syncthreads per k64 chunk.
#define MAINLOOP(NK, pA, sA, pB, sB)                                          \
    stage_panels(sb, t, pA, sA, pB, sB); CP_COMMIT();                         \
    stage_panels(sb + STG, t, pA + 64, sA, pB + 64, sB); CP_COMMIT();         \
    _Pragma("unroll 1")                                                       \
    for (int kt = 0; kt < (NK); kt++) {                                       \
        if (kt + 1 < (NK)) { CP_WAIT1(); } else { CP_WAIT0(); }               \
        __syncthreads();                                                      \
        if (kt + 2 < (NK)) {                                                  \
            int bi = (kt + 2) % 3;                                            \
            stage_panels(sb + (uint32_t)bi * STG, t,                          \
                         pA + (kt + 2) * 64, sA, pB + (kt + 2) * 64, sB);     \
            CP_COMMIT();                                                      \
        }                                                                     \
        mma_block128(sb + (uint32_t)(kt % 3) * STG, wm, wn, lr, kc, d);       \
    }

// =====================================================================
// GEMM1 (v = x @ V^T) + fused expert chain -> c'
// grid (BATCH/128, 4), 256 threads, 2 CTAs/SM
// =====================================================================
__global__ void __launch_bounds__(256, 2) gemm1_k(int l) {
    extern __shared__ char smc[];
    const uint32_t sb = smem_u32(smc);
    const int t = threadIdx.x, w = t >> 5, lane = t & 31;
    const int lr = lane & 15, kc = (lane >> 4) * 8, g = lane >> 2, tig = lane & 3;
    const int wm = (w & 3) * 32, wn = (w >> 2) * 64;
    const size_t brow0 = (size_t)blockIdx.x * 128;

    const __half* pA = g_xh + brow0 * NN;
    const __half* pB = g_Vh + (size_t)l * ER * NN + (size_t)(blockIdx.y * 128) * NN;

    float d[2][8][4];
#pragma unroll
    for (int i = 0; i < 2; i++)
#pragma unroll
        for (int j = 0; j < 8; j++)
#pragma unroll
            for (int k = 0; k < 4; k++) d[i][j][k] = 0.f;

    MAINLOOP(16, pA, NN, pB, NN)
    __syncthreads();   // mainloop done before smem reuse

    // ---- write relu(v) -> rv tiles (pitch 144, expert el = w>>2) ----
    const int el = w >> 2;
    {
#pragma unroll
        for (int i = 0; i < 2; i++) {
            int r0 = wm + i * 16 + g;
#pragma unroll
            for (int j = 0; j < 8; j++) {
                int c = j * 8 + 2 * tig;
                uint32_t h0 = hpack2(fmaxf(d[i][j][0], 0.f), fmaxf(d[i][j][1], 0.f));
                uint32_t h1 = hpack2(fmaxf(d[i][j][2], 0.f), fmaxf(d[i][j][3], 0.f));
                uint32_t o0 = (uint32_t)(r0 * 144 + c * 2);
                *(uint32_t*)(smc + RV_H(el) + o0)           = h0;
                *(uint32_t*)(smc + RV_H(el) + o0 + 8 * 144) = h1;
            }
        }
    }
    // ---- load C tiles (2 experts) ----
    {
        int el2 = t >> 7, r = (t >> 1) & 63, hf = t & 1;
        const __half* sH = g_Ch +
            (((size_t)(l * EE + blockIdx.y * 2 + el2)) * RR + r) * RR + hf * 32;
        char* dH = smc + OCT + el2 * 9216 + r * 144 + hf * 64;
#pragma unroll
        for (int s4 = 0; s4 < 4; s4++)
            *(uint4*)(dH + s4 * 16) = *(const uint4*)(sH + s4 * 8);
    }
    __syncthreads();

    // ---- expert mma: c = rv @ C_e^T  (K=64) ----
#pragma unroll
    for (int i = 0; i < 2; i++)
#pragma unroll
        for (int j = 0; j < 8; j++)
#pragma unroll
            for (int k = 0; k < 4; k++) d[i][j][k] = 0.f;
    {
        const uint32_t Ah = sb + RV_H(el);
        const uint32_t Bh = sb + OCT + el * 9216;
#pragma unroll
        for (int q = 0; q < 4; q++) {
            uint32_t ah[2][4];
#pragma unroll
            for (int i = 0; i < 2; i++) {
                uint32_t ra = (uint32_t)((wm + i * 16 + lr) * 144 + (q * 16 + kc) * 2);
                ldsm4(ah[i], Ah + ra);
            }
            uint32_t bh[8][2];
#pragma unroll
            for (int jj = 0; jj < 4; jj++) {
                uint32_t rb = (uint32_t)((jj * 16 + lr) * 144 + (q * 16 + kc) * 2);
                uint32_t tp[4];
                ldsm4(tp, Bh + rb);
                bh[2 * jj][0] = tp[0]; bh[2 * jj + 1][0] = tp[1];
                bh[2 * jj][1] = tp[2]; bh[2 * jj + 1][1] = tp[3];
            }
#pragma unroll
            for (int i = 0; i < 2; i++)
#pragma unroll
                for (int j = 0; j < 8; j++)
                    mma_f16(d[i][j], ah[i], bh[j]);
        }
    }

    // ---- epilogue: c' = gate*relu(c) -> global fp16 ----
    {
        const int e = blockIdx.y * 2 + el;
#pragma unroll
        for (int i = 0; i < 2; i++) {
            size_t r0 = brow0 + wm + i * 16 + g, r1 = r0 + 8;
            float g0 = g_gates[r0 * EE + e], g1 = g_gates[r1 * EE + e];
#pragma unroll
            for (int j = 0; j < 8; j++) {
                int cc = e * 64 + j * 8 + 2 * tig;
                *(uint32_t*)(g_cph + r0 * ER + cc) =
                    hpack2(g0 * fmaxf(d[i][j][0], 0.f), g0 * fmaxf(d[i][j][1], 0.f));
                *(uint32_t*)(g_cph + r1 * ER + cc) =
                    hpack2(g1 * fmaxf(d[i][j][2], 0.f), g1 * fmaxf(d[i][j][3], 0.f));
            }
        }
    }
}

// =====================================================================
// GEMM2: x_next = x0 * (c' @ U^T + bias) + x_l ; emits fp16 x_next
// grid (BATCH/128, 8), 256 threads, 2 CTAs/SM
// =====================================================================
__global__ void __launch_bounds__(256, 2) gemm2_k(const float* __restrict__ x_in,
                                                  const float* __restrict__ biasg,
                                                  float* __restrict__ outg, int l) {
    extern __shared__ char smc[];
    const uint32_t sb = smem_u32(smc);
    const int t = threadIdx.x, w = t >> 5, lane = t & 31;
    const int lr = lane & 15, kc = (lane >> 4) * 8, g = lane >> 2, tig = lane & 3;
    const int wm = (w & 3) * 32, wn = (w >> 2) * 64;
    const size_t brow0 = (size_t)blockIdx.x * 128;
    const int no = blockIdx.y * 128;

    const __half* pA = g_cph + brow0 * ER;
    const __half* pB = g_Uh + (size_t)l * NN * ER + (size_t)no * ER;

    float d[2][8][4];
#pragma unroll
    for (int i = 0; i < 2; i++)
#pragma unroll
        for (int j = 0; j < 8; j++)
#pragma unroll
            for (int k = 0; k < 4; k++) d[i][j][k] = 0.f;

    MAINLOOP(8, pA, ER, pB, ER)

    // ---- epilogue (fp32 residual path — exact) ----
    const float* xl = l ? g_xcur : x_in;
    float* dst = (l == LL - 1) ? outg : g_xcur;
#pragma unroll
    for (int i = 0; i < 2; i++) {
        size_t r0 = brow0 + wm + i * 16 + g, r1 = r0 + 8;
#pragma unroll
        for (int j = 0; j < 8; j++) {
            int c0 = no + wn + j * 8 + 2 * tig;
            float2 bv = *(const float2*)(biasg + l * NN + c0);
            {
                float2 xv = *(const float2*)(x_in + r0 * NN + c0);
                float2 lv = *(const float2*)(xl + r0 * NN + c0);
                float o0 = fmaf(xv.x, d[i][j][0] + bv.x, lv.x);
                float o1 = fmaf(xv.y, d[i][j][1] + bv.y, lv.y);
                *(float2*)(dst + r0 * NN + c0) = make_float2(o0, o1);
                if (l < LL - 1)
                    *(uint32_t*)(g_xh + r0 * NN + c0) = hpack2(o0, o1);
            }
            {
                float2 xv = *(const float2*)(x_in + r1 * NN + c0);
                float2 lv = *(const float2*)(xl + r1 * NN + c0);
                float o0 = fmaf(xv.x, d[i][j][2] + bv.x, lv.x);
                float o1 = fmaf(xv.y, d[i][j][3] + bv.y, lv.y);
                *(float2*)(dst + r1 * NN + c0) = make_float2(o0, o1);
                if (l < LL - 1)
                    *(uint32_t*)(g_xh + r1 * NN + c0) = hpack2(o0, o1);
            }
        }
    }
}

// =====================================================================
extern "C" void kernel_launch(void* const* d_in, const int* in_sizes, int n_in,
                              void* d_out, int out_size) {
    const float* x    = (const float*)d_in[0];
    const float* U    = (const float*)d_in[1];
    const float* V    = (const float*)d_in[2];
    const float* C    = (const float*)d_in[3];
    const float* bias = (const float*)d_in[4];
    const float* gw   = (const float*)d_in[5];
    float* out = (float*)d_out;

    prep_x<<<BATCH * NN / 256, 256>>>(x);
    prepV_k<<<LL * ER * NN / 256, 256>>>(V);
    prepU_k<<<LL * NN * ER / 256, 256>>>(U);
    prepC_k<<<LL * EE * RR * RR / 256, 256>>>(C);

    cudaFuncSetAttribute(gemm1_k, cudaFuncAttributeMaxDynamicSharedMemorySize, SM_SZ);
    cudaFuncSetAttribute(gemm2_k, cudaFuncAttributeMaxDynamicSharedMemorySize, SM_SZ);

    for (int l = 0; l < LL; l++) {
        gates_k<<<BATCH / 8, 256>>>(gw);
        gemm1_k<<<dim3(BATCH / 128, 4), 256, SM_SZ>>>(l);
        gemm2_k<<<dim3(BATCH / 128, 8), 256, SM_SZ>>>(x, bias, out, l);
    }
}

// round 13
// speedup vs baseline: 1.2214x; 1.0449x over previous
#include <cuda_runtime.h>
#include <cuda_fp16.h>
#include <cstdint>

#define BATCH 16384
#define NN    1024
#define EE    8
#define RR    64
#define ER    512
#define LL    3

// ---------------- static device scratch ----------------
__device__ float   g_xcur[BATCH * NN];
__device__ float   g_gates[BATCH * EE];
__device__ __half  g_xh[BATCH * NN];            // x_l fp16
__device__ __half  g_cph[BATCH * ER];           // c' fp16
__device__ __half  g_Vh[LL * ER * NN];          // weights fp16
__device__ __half  g_Uh[LL * NN * ER];
__device__ __half  g_Ch[LL * EE * RR * RR];

// ---------------- helpers ----------------
__device__ __forceinline__ uint32_t smem_u32(const void* p) {
    uint32_t a;
    asm("{ .reg .u64 t; cvta.to.shared.u64 t, %1; cvt.u32.u64 %0, t; }" : "=r"(a) : "l"(p));
    return a;
}
__device__ __forceinline__ void ldsm4(uint32_t* r, uint32_t addr) {
    asm volatile("ldmatrix.sync.aligned.m8n8.x4.shared.b16 {%0,%1,%2,%3}, [%4];"
                 : "=r"(r[0]), "=r"(r[1]), "=r"(r[2]), "=r"(r[3]) : "r"(addr));
}
__device__ __forceinline__ void mma_f16(float* d, const uint32_t* a, const uint32_t* b) {
    asm volatile(
        "mma.sync.aligned.m16n8k16.row.col.f32.f16.f16.f32 "
        "{%0,%1,%2,%3}, {%4,%5,%6,%7}, {%8,%9}, {%0,%1,%2,%3};"
        : "+f"(d[0]), "+f"(d[1]), "+f"(d[2]), "+f"(d[3])
        : "r"(a[0]), "r"(a[1]), "r"(a[2]), "r"(a[3]), "r"(b[0]), "r"(b[1]));
}
__device__ __forceinline__ uint32_t hpack2(float a, float b) {
    __half ha = __float2half_rn(a), hb = __float2half_rn(b);
    return (uint32_t)__half_as_ushort(ha) | ((uint32_t)__half_as_ushort(hb) << 16);
}
__device__ __forceinline__ void cp16(uint32_t dst, const void* src) {
    asm volatile("cp.async.cg.shared.global [%0], [%1], 16;" :: "r"(dst), "l"(src));
}
#define CP_COMMIT() asm volatile("cp.async.commit_group;" ::: "memory")
#define CP_WAIT1()  asm volatile("cp.async.wait_group 1;" ::: "memory")
#define CP_WAIT0()  asm volatile("cp.async.wait_group 0;" ::: "memory")

// ---------------- prep kernels ----------------
__global__ void prep_x(const float* __restrict__ x) {
    int i = blockIdx.x * 256 + threadIdx.x;
    g_xh[i] = __float2half_rn(x[i]);
}
// fused V + C conversion (V: 1572864 elems, C: 98304 elems)
__global__ void prepVC_k(const float* __restrict__ V, const float* __restrict__ C) {
    int i = blockIdx.x * 256 + threadIdx.x;
    if (i < LL * ER * NN) g_Vh[i] = __float2half_rn(V[i]);
    int j = i - LL * ER * NN;
    if (j >= 0 && j < LL * EE * RR * RR) g_Ch[j] = __float2half_rn(C[j]);
}
__global__ void prepU_k(const float* __restrict__ U) {
    int o = blockIdx.x * 256 + threadIdx.x;     // o = (l*NN + n)*ER + er
    int er = o & 511, n = (o >> 9) & 1023, l = o >> 19;
    g_Uh[o] = __float2half_rn(U[(((size_t)(l * EE + (er >> 6))) * NN + n) * RR + (er & 63)]);
}

// ---------------- gates (exact fp32 — R10 version) ----------------
__global__ void gates_k(const float* __restrict__ x_in, const float* __restrict__ gw, int l) {
    const float* xl = l ? g_xcur : x_in;
    int w = threadIdx.x >> 5, lane = threadIdx.x & 31;
    size_t row = (size_t)blockIdx.x * 8 + w;
    const float4* xr = (const float4*)(xl + row * NN);
    float acc[EE];
#pragma unroll
    for (int e = 0; e < EE; e++) acc[e] = 0.f;
#pragma unroll
    for (int i = 0; i < 8; i++) {
        float4 xv = xr[i * 32 + lane];
#pragma unroll
        for (int e = 0; e < EE; e++) {
            float4 wv = ((const float4*)(gw + e * NN))[i * 32 + lane];
            acc[e] += xv.x * wv.x + xv.y * wv.y + xv.z * wv.z + xv.w * wv.w;
        }
    }
#pragma unroll
    for (int off = 16; off > 0; off >>= 1)
#pragma unroll
        for (int e = 0; e < EE; e++) acc[e] += __shfl_xor_sync(0xffffffffu, acc[e], off);
    if (lane == 0) {
        float m = acc[0];
#pragma unroll
        for (int e = 1; e < EE; e++) m = fmaxf(m, acc[e]);
        float s = 0.f, pe[EE];
#pragma unroll
        for (int e = 0; e < EE; e++) { pe[e] = __expf(acc[e] - m); s += pe[e]; }
        float inv = 1.0f / s;
#pragma unroll
        for (int e = 0; e < EE; e++) g_gates[row * EE + e] = pe[e] * inv;
    }
}

// ---------------- stage layout (bytes) ----------------
// per stage (36864): A[128][144] @0, B[128][144] @18432 ; 3 stages; K-chunk 64
#define STG   36864
#define S_BH  18432
#define RV_H(el)  ((el) * 18432)
#define OCT       36864
#define SM_SZ     110592

// cp.async stage: A 128 rows x 128B, B 128 rows x 128B  (8 cp16 / thread)
__device__ __forceinline__ void stage_panels(
    uint32_t sbase, int t,
    const __half* A, int strideA, const __half* B, int strideB) {
    const int row = t >> 3;
    const uint32_t seg = (uint32_t)(t & 7) * 16;
#pragma unroll
    for (int it = 0; it < 4; it++) {
        int r = it * 32 + row;
        cp16(sbase + (uint32_t)r * 144 + seg, (const char*)(A + (size_t)r * strideA) + seg);
        cp16(sbase + S_BH + (uint32_t)r * 144 + seg,
             (const char*)(B + (size_t)r * strideB) + seg);
    }
}

// ---------------- 128x128 tile, one k64 chunk; warp tile 32x64 ----------------
__device__ __forceinline__ void mma_block128(uint32_t base, int wm, int wn, int lr, int kc,
                                             float d[2][8][4]) {
    const uint32_t Ah = base, Bh = base + S_BH;
#pragma unroll
    for (int q = 0; q < 4; q++) {
        uint32_t ah[2][4];
#pragma unroll
        for (int i = 0; i < 2; i++) {
            uint32_t ra = (uint32_t)((wm + i * 16 + lr) * 144 + (q * 16 + kc) * 2);
            ldsm4(ah[i], Ah + ra);
        }
        uint32_t bh[8][2];
#pragma unroll
        for (int jj = 0; jj < 4; jj++) {
            uint32_t rb = (uint32_t)((wn + jj * 16 + lr) * 144 + (q * 16 + kc) * 2);
            uint32_t tp[4];
            ldsm4(tp, Bh + rb);
            bh[2 * jj][0] = tp[0]; bh[2 * jj + 1][0] = tp[1];
            bh[2 * jj][1] = tp[2]; bh[2 * jj + 1][1] = tp[3];
        }
#pragma unroll
        for (int i = 0; i < 2; i++)
#pragma unroll
            for (int j = 0; j < 8; j++)
                mma_f16(d[i][j], ah[i], bh[j]);
    }
}

// 3-buffer mainloop, ONE __syncthreads per k64 chunk.
#define MAINLOOP(NK, pA, sA, pB, sB)                                          \
    stage_panels(sb, t, pA, sA, pB, sB); CP_COMMIT();                         \
    stage_panels(sb + STG, t, pA + 64, sA, pB + 64, sB); CP_COMMIT();         \
    _Pragma("unroll 1")                                                       \
    for (int kt = 0; kt < (NK); kt++) {                                       \
        if (kt + 1 < (NK)) { CP_WAIT1(); } else { CP_WAIT0(); }               \
        __syncthreads();                                                      \
        if (kt + 2 < (NK)) {                                                  \
            int bi = (kt + 2) % 3;                                            \
            stage_panels(sb + (uint32_t)bi * STG, t,                          \
                         pA + (kt + 2) * 64, sA, pB + (kt + 2) * 64, sB);     \
            CP_COMMIT();                                                      \
        }                                                                     \
        mma_block128(sb + (uint32_t)(kt % 3) * STG, wm, wn, lr, kc, d);       \
    }

// =====================================================================
// GEMM1 (v = x @ V^T) + fused expert chain -> c'
// grid (BATCH/128, 4), 256 threads, 2 CTAs/SM
// =====================================================================
__global__ void __launch_bounds__(256, 2) gemm1_k(int l) {
    extern __shared__ char smc[];
    const uint32_t sb = smem_u32(smc);
    const int t = threadIdx.x, w = t >> 5, lane = t & 31;
    const int lr = lane & 15, kc = (lane >> 4) * 8, g = lane >> 2, tig = lane & 3;
    const int wm = (w & 3) * 32, wn = (w >> 2) * 64;
    const size_t brow0 = (size_t)blockIdx.x * 128;

    const __half* pA = g_xh + brow0 * NN;
    const __half* pB = g_Vh + (size_t)l * ER * NN + (size_t)(blockIdx.y * 128) * NN;

    float d[2][8][4];
#pragma unroll
    for (int i = 0; i < 2; i++)
#pragma unroll
        for (int j = 0; j < 8; j++)
#pragma unroll
            for (int k = 0; k < 4; k++) d[i][j][k] = 0.f;

    MAINLOOP(16, pA, NN, pB, NN)
    __syncthreads();   // mainloop done before smem reuse

    // ---- write relu(v) -> rv tiles (pitch 144, expert el = w>>2) ----
    const int el = w >> 2;
    {
#pragma unroll
        for (int i = 0; i < 2; i++) {
            int r0 = wm + i * 16 + g;
#pragma unroll
            for (int j = 0; j < 8; j++) {
                int c = j * 8 + 2 * tig;
                uint32_t h0 = hpack2(fmaxf(d[i][j][0], 0.f), fmaxf(d[i][j][1], 0.f));
                uint32_t h1 = hpack2(fmaxf(d[i][j][2], 0.f), fmaxf(d[i][j][3], 0.f));
                uint32_t o0 = (uint32_t)(r0 * 144 + c * 2);
                *(uint32_t*)(smc + RV_H(el) + o0)           = h0;
                *(uint32_t*)(smc + RV_H(el) + o0 + 8 * 144) = h1;
            }
        }
    }
    // ---- load C tiles (2 experts) ----
    {
        int el2 = t >> 7, r = (t >> 1) & 63, hf = t & 1;
        const __half* sH = g_Ch +
            (((size_t)(l * EE + blockIdx.y * 2 + el2)) * RR + r) * RR + hf * 32;
        char* dH = smc + OCT + el2 * 9216 + r * 144 + hf * 64;
#pragma unroll
        for (int s4 = 0; s4 < 4; s4++)
            *(uint4*)(dH + s4 * 16) = *(const uint4*)(sH + s4 * 8);
    }
    __syncthreads();

    // ---- expert mma: c = rv @ C_e^T  (K=64) ----
#pragma unroll
    for (int i = 0; i < 2; i++)
#pragma unroll
        for (int j = 0; j < 8; j++)
#pragma unroll
            for (int k = 0; k < 4; k++) d[i][j][k] = 0.f;
    {
        const uint32_t Ah = sb + RV_H(el);
        const uint32_t Bh = sb + OCT + el * 9216;
#pragma unroll
        for (int q = 0; q < 4; q++) {
            uint32_t ah[2][4];
#pragma unroll
            for (int i = 0; i < 2; i++) {
                uint32_t ra = (uint32_t)((wm + i * 16 + lr) * 144 + (q * 16 + kc) * 2);
                ldsm4(ah[i], Ah + ra);
            }
            uint32_t bh[8][2];
#pragma unroll
            for (int jj = 0; jj < 4; jj++) {
                uint32_t rb = (uint32_t)((jj * 16 + lr) * 144 + (q * 16 + kc) * 2);
                uint32_t tp[4];
                ldsm4(tp, Bh + rb);
                bh[2 * jj][0] = tp[0]; bh[2 * jj + 1][0] = tp[1];
                bh[2 * jj][1] = tp[2]; bh[2 * jj + 1][1] = tp[3];
            }
#pragma unroll
            for (int i = 0; i < 2; i++)
#pragma unroll
                for (int j = 0; j < 8; j++)
                    mma_f16(d[i][j], ah[i], bh[j]);
        }
    }

    // ---- epilogue: c' = gate*relu(c) -> global fp16 ----
    {
        const int e = blockIdx.y * 2 + el;
#pragma unroll
        for (int i = 0; i < 2; i++) {
            size_t r0 = brow0 + wm + i * 16 + g, r1 = r0 + 8;
            float g0 = g_gates[r0 * EE + e], g1 = g_gates[r1 * EE + e];
#pragma unroll
            for (int j = 0; j < 8; j++) {
                int cc = e * 64 + j * 8 + 2 * tig;
                *(uint32_t*)(g_cph + r0 * ER + cc) =
                    hpack2(g0 * fmaxf(d[i][j][0], 0.f), g0 * fmaxf(d[i][j][1], 0.f));
                *(uint32_t*)(g_cph + r1 * ER + cc) =
                    hpack2(g1 * fmaxf(d[i][j][2], 0.f), g1 * fmaxf(d[i][j][3], 0.f));
            }
        }
    }
}

// =====================================================================
// GEMM2: x_next = x0 * (c' @ U^T + bias) + x_l ; emits fp16 x_next
// grid (BATCH/128, 8), 256 threads, 2 CTAs/SM
// =====================================================================
__global__ void __launch_bounds__(256, 2) gemm2_k(const float* __restrict__ x_in,
                                                  const float* __restrict__ biasg,
                                                  float* __restrict__ outg, int l) {
    extern __shared__ char smc[];
    const uint32_t sb = smem_u32(smc);
    const int t = threadIdx.x, w = t >> 5, lane = t & 31;
    const int lr = lane & 15, kc = (lane >> 4) * 8, g = lane >> 2, tig = lane & 3;
    const int wm = (w & 3) * 32, wn = (w >> 2) * 64;
    const size_t brow0 = (size_t)blockIdx.x * 128;
    const int no = blockIdx.y * 128;

    const __half* pA = g_cph + brow0 * ER;
    const __half* pB = g_Uh + (size_t)l * NN * ER + (size_t)no * ER;

    float d[2][8][4];
#pragma unroll
    for (int i = 0; i < 2; i++)
#pragma unroll
        for (int j = 0; j < 8; j++)
#pragma unroll
            for (int k = 0; k < 4; k++) d[i][j][k] = 0.f;

    MAINLOOP(8, pA, ER, pB, ER)

    // ---- epilogue (fp32 residual path — exact) ----
    const float* xl = l ? g_xcur : x_in;
    float* dst = (l == LL - 1) ? outg : g_xcur;
#pragma unroll
    for (int i = 0; i < 2; i++) {
        size_t r0 = brow0 + wm + i * 16 + g, r1 = r0 + 8;
#pragma unroll
        for (int j = 0; j < 8; j++) {
            int c0 = no + wn + j * 8 + 2 * tig;
            float2 bv = *(const float2*)(biasg + l * NN + c0);
            {
                float2 xv = *(const float2*)(x_in + r0 * NN + c0);
                float2 lv = *(const float2*)(xl + r0 * NN + c0);
                float o0 = fmaf(xv.x, d[i][j][0] + bv.x, lv.x);
                float o1 = fmaf(xv.y, d[i][j][1] + bv.y, lv.y);
                *(float2*)(dst + r0 * NN + c0) = make_float2(o0, o1);
                if (l < LL - 1)
                    *(uint32_t*)(g_xh + r0 * NN + c0) = hpack2(o0, o1);
            }
            {
                float2 xv = *(const float2*)(x_in + r1 * NN + c0);
                float2 lv = *(const float2*)(xl + r1 * NN + c0);
                float o0 = fmaf(xv.x, d[i][j][2] + bv.x, lv.x);
                float o1 = fmaf(xv.y, d[i][j][3] + bv.y, lv.y);
                *(float2*)(dst + r1 * NN + c0) = make_float2(o0, o1);
                if (l < LL - 1)
                    *(uint32_t*)(g_xh + r1 * NN + c0) = hpack2(o0, o1);
            }
        }
    }
}

// =====================================================================
extern "C" void kernel_launch(void* const* d_in, const int* in_sizes, int n_in,
                              void* d_out, int out_size) {
    const float* x    = (const float*)d_in[0];
    const float* U    = (const float*)d_in[1];
    const float* V    = (const float*)d_in[2];
    const float* C    = (const float*)d_in[3];
    const float* bias = (const float*)d_in[4];
    const float* gw   = (const float*)d_in[5];
    float* out = (float*)d_out;

    cudaFuncSetAttribute(gemm1_k, cudaFuncAttributeMaxDynamicSharedMemorySize, SM_SZ);
    cudaFuncSetAttribute(gemm2_k, cudaFuncAttributeMaxDynamicSharedMemorySize, SM_SZ);

    const int VC_N = LL * ER * NN + LL * EE * RR * RR;   // 1671168
    // Launch order chosen so gemm1_k (layer 0) is the 4th launch -> ncu profiles it.
    prep_x<<<BATCH * NN / 256, 256>>>(x);                       // 1
    prepVC_k<<<(VC_N + 255) / 256, 256>>>(V, C);                // 2
    gates_k<<<BATCH / 8, 256>>>(x, gw, 0);                      // 3
    gemm1_k<<<dim3(BATCH / 128, 4), 256, SM_SZ>>>(0);           // 4 <- profiled
    prepU_k<<<LL * NN * ER / 256, 256>>>(U);                    // 5
    gemm2_k<<<dim3(BATCH / 128, 8), 256, SM_SZ>>>(x, bias, out, 0);
    for (int l = 1; l < LL; l++) {
        gates_k<<<BATCH / 8, 256>>>(x, gw, l);
        gemm1_k<<<dim3(BATCH / 128, 4), 256, SM_SZ>>>(l);
        gemm2_k<<<dim3(BATCH / 128, 8), 256, SM_SZ>>>(x, bias, out, l);
    }
}